// round 8
// baseline (speedup 1.0000x reference)
#include <cuda_runtime.h>
#include <cuda_fp16.h>
#include <cstdint>
#include <math.h>

#define DSIZE 4096
#define NELEM ((size_t)DSIZE * (size_t)DSIZE)

// Static __device__ scratch (sanctioned no-alloc mechanism): 6 x 32 MB fp16
__device__ __align__(256) __half g_ah[NELEM];
__device__ __align__(256) __half g_al[NELEM];
__device__ __align__(256) __half g_bh[NELEM];
__device__ __align__(256) __half g_bl[NELEM];
__device__ __align__(256) __half g_hh[NELEM];
__device__ __align__(256) __half g_hl[NELEM];

// ---------------------------------------------------------------- tile config
#define BM 128
#define BN 256
#define BK 32
#define NTHREADS 256
#define STAGES 4
#define NCHUNK (DSIZE / BK)            // 128

// 64-byte rows (BK=32 fp16). A tile: 128 rows, B tile: 256 rows, hi+lo each.
#define OFF_AH 0
#define OFF_AL 8192
#define OFF_BH 16384
#define OFF_BL 32768
#define STAGE_BYTES 49152
#define SMEM_TOTAL (STAGES * STAGE_BYTES)   // 196608

// ---------------------------------------------------------------- asm helpers
__device__ __forceinline__ uint32_t smem_u32(const void* p) {
    uint32_t a;
    asm("{ .reg .u64 t; cvta.to.shared.u64 t, %1; cvt.u32.u64 %0, t; }" : "=r"(a) : "l"(p));
    return a;
}
#define CP_COMMIT() asm volatile("cp.async.commit_group;" ::: "memory")
#define CP_WAIT(N)  asm volatile("cp.async.wait_group %0;" :: "n"(N) : "memory")

__device__ __forceinline__ void ldsm4(uint32_t* r, uint32_t addr) {
    asm volatile("ldmatrix.sync.aligned.m8n8.x4.shared.b16 {%0,%1,%2,%3}, [%4];"
                 : "=r"(r[0]), "=r"(r[1]), "=r"(r[2]), "=r"(r[3]) : "r"(addr));
}
__device__ __forceinline__ void mma16816(float* d, const uint32_t* a, const uint32_t* b) {
    asm volatile("mma.sync.aligned.m16n8k16.row.col.f32.f16.f16.f32 "
                 "{%0,%1,%2,%3}, {%4,%5,%6,%7}, {%8,%9}, {%0,%1,%2,%3};"
                 : "+f"(d[0]), "+f"(d[1]), "+f"(d[2]), "+f"(d[3])
                 : "r"(a[0]), "r"(a[1]), "r"(a[2]), "r"(a[3]), "r"(b[0]), "r"(b[1]));
}

// Copy one [NROWS x 32 fp16] tile (64B rows) into XOR-swizzled smem.
// Swizzle: seg' = seg ^ ((row >> 1) & 3) — conflict-free STS.128 + ldmatrix.
template <int NROWS>
__device__ __forceinline__ void load_tile(uint32_t dst, const __half* src,
                                          int row0, int k0, int tid) {
    const char* gbase = reinterpret_cast<const char*>(src + (size_t)row0 * DSIZE + k0);
    #pragma unroll
    for (int t = 0; t < NROWS * 4 / NTHREADS; t++) {
        const int i = tid + t * NTHREADS;
        const uint32_t r = (uint32_t)i >> 2;
        const uint32_t seg = (uint32_t)i & 3;
        const uint32_t sw = seg ^ ((r >> 1) & 3);
        asm volatile("cp.async.cg.shared.global [%0], [%1], 16;"
                     :: "r"(dst + r * 64 + sw * 16),
                        "l"(gbase + (size_t)r * (DSIZE * 2) + seg * 16));
    }
}

__device__ __forceinline__ void load_stage(uint32_t st,
                                           const __half* Ah, const __half* Al,
                                           const __half* Bh, const __half* Bl,
                                           int bm, int bn, int k0, int tid) {
    load_tile<BM>(st + OFF_AH, Ah, bm, k0, tid);
    load_tile<BM>(st + OFF_AL, Al, bm, k0, tid);
    load_tile<BN>(st + OFF_BH, Bh, bn, k0, tid);
    load_tile<BN>(st + OFF_BL, Bl, bn, k0, tid);
}

// ---------------------------------------------------------------- GEMM kernel
// C = (Ah+Al) @ (Bh+Bl)^T + bias, via 3 HMMA products (AlBl dropped, ~2^-22).
// Warp tile 64x64: 8 warps as 2(M) x 4(N). acc[4 mtiles][8 ntiles][4].
// MODE 0: write fp16 hi/lo split of result. MODE 1: write flip(cos(result)) fp32.
template <int MODE>
__global__ __launch_bounds__(NTHREADS, 1)
void gemm_split3(const __half* __restrict__ Ah, const __half* __restrict__ Al,
                 const __half* __restrict__ Bh, const __half* __restrict__ Bl,
                 const float* __restrict__ bias,
                 float* __restrict__ outF,
                 __half* __restrict__ outH, __half* __restrict__ outL)
{
    extern __shared__ __align__(1024) char smem[];
    const uint32_t sb = smem_u32(smem);

    const int tid = threadIdx.x;
    const int lane = tid & 31;
    const int wid = tid >> 5;
    const int warp_m = wid & 1;       // 2 warps along M, 64 rows each
    const int warp_n = wid >> 1;      // 4 warps along N, 64 cols each
    const int bm = blockIdx.y * BM;
    const int bn = blockIdx.x * BN;

    float acc[4][8][4];
    #pragma unroll
    for (int mt = 0; mt < 4; mt++)
        #pragma unroll
        for (int nt = 0; nt < 8; nt++)
            #pragma unroll
            for (int j = 0; j < 4; j++)
                acc[mt][nt][j] = 0.0f;

    // Prologue: fill STAGES-1 pipeline stages
    #pragma unroll
    for (int s = 0; s < STAGES - 1; s++) {
        load_stage(sb + s * STAGE_BYTES, Ah, Al, Bh, Bl, bm, bn, s * BK, tid);
        CP_COMMIT();
    }

    for (int k = 0; k < NCHUNK; k++) {
        CP_WAIT(STAGES - 2);
        __syncthreads();

        const int kn = k + STAGES - 1;
        if (kn < NCHUNK)
            load_stage(sb + (kn & (STAGES - 1)) * STAGE_BYTES,
                       Ah, Al, Bh, Bl, bm, bn, kn * BK, tid);
        CP_COMMIT();   // commit (possibly empty) group to keep wait counts consistent

        const uint32_t sa = sb + (k & (STAGES - 1)) * STAGE_BYTES;

        #pragma unroll
        for (int ks = 0; ks < 2; ks++) {
            // A fragments: 4 m-tiles x (hi, lo) = 32 regs
            uint32_t afh[4][4], afl[4][4];
            #pragma unroll
            for (int mt = 0; mt < 4; mt++) {
                const uint32_t row = warp_m * 64 + mt * 16 + (lane & 15);
                const uint32_t seg = ks * 2 + (lane >> 4);
                const uint32_t off = row * 64 + ((seg ^ ((row >> 1) & 3)) << 4);
                ldsm4(afh[mt], sa + OFF_AH + off);
                ldsm4(afl[mt], sa + OFF_AL + off);
            }
            // B fragments streamed pair-by-pair (keeps live B regs at 8)
            #pragma unroll
            for (int p = 0; p < 4; p++) {
                const uint32_t n = warp_n * 64 + p * 16 + ((lane >> 4) << 3) + (lane & 7);
                const uint32_t seg = ks * 2 + ((lane >> 3) & 1);
                const uint32_t off = n * 64 + ((seg ^ ((n >> 1) & 3)) << 4);
                uint32_t th[4], tl[4];
                ldsm4(th, sa + OFF_BH + off);
                ldsm4(tl, sa + OFF_BL + off);
                #pragma unroll
                for (int mt = 0; mt < 4; mt++) {
                    mma16816(acc[mt][2 * p],     afh[mt], th);
                    mma16816(acc[mt][2 * p + 1], afh[mt], th + 2);
                    mma16816(acc[mt][2 * p],     afl[mt], th);
                    mma16816(acc[mt][2 * p + 1], afl[mt], th + 2);
                    mma16816(acc[mt][2 * p],     afh[mt], tl);
                    mma16816(acc[mt][2 * p + 1], afh[mt], tl + 2);
                }
            }
        }
    }

    // ---------------------------------------------------------------- epilogue
    const int g = lane >> 2;
    const int tig = lane & 3;
    #pragma unroll
    for (int mt = 0; mt < 4; mt++) {
        #pragma unroll
        for (int nt = 0; nt < 8; nt++) {
            const int col = bn + warp_n * 64 + nt * 8 + tig * 2;
            const float2 bv = *reinterpret_cast<const float2*>(bias + col);
            const int r0 = bm + warp_m * 64 + mt * 16 + g;
            const float* a = acc[mt][nt];
            float v00 = a[0] + bv.x, v01 = a[1] + bv.y;   // row r0
            float v10 = a[2] + bv.x, v11 = a[3] + bv.y;   // row r0+8
            if (MODE == 1) {
                float c;
                c = cosf(v00); if (fabsf(c) < 0.01f) c = -c; v00 = c;
                c = cosf(v01); if (fabsf(c) < 0.01f) c = -c; v01 = c;
                c = cosf(v10); if (fabsf(c) < 0.01f) c = -c; v10 = c;
                c = cosf(v11); if (fabsf(c) < 0.01f) c = -c; v11 = c;
                *reinterpret_cast<float2*>(outF + (size_t)r0 * DSIZE + col) =
                    make_float2(v00, v01);
                *reinterpret_cast<float2*>(outF + (size_t)(r0 + 8) * DSIZE + col) =
                    make_float2(v10, v11);
            } else {
                const __half h00 = __float2half_rn(v00), h01 = __float2half_rn(v01);
                const __half h10 = __float2half_rn(v10), h11 = __float2half_rn(v11);
                const __half l00 = __float2half_rn(v00 - __half2float(h00));
                const __half l01 = __float2half_rn(v01 - __half2float(h01));
                const __half l10 = __float2half_rn(v10 - __half2float(h10));
                const __half l11 = __float2half_rn(v11 - __half2float(h11));
                *reinterpret_cast<__half2*>(outH + (size_t)r0 * DSIZE + col) =
                    __halves2half2(h00, h01);
                *reinterpret_cast<__half2*>(outH + (size_t)(r0 + 8) * DSIZE + col) =
                    __halves2half2(h10, h11);
                *reinterpret_cast<__half2*>(outL + (size_t)r0 * DSIZE + col) =
                    __halves2half2(l00, l01);
                *reinterpret_cast<__half2*>(outL + (size_t)(r0 + 8) * DSIZE + col) =
                    __halves2half2(l10, l11);
            }
        }
    }
}

// ---------------------------------------------------------------- fp32 -> fp16 hi/lo
__global__ __launch_bounds__(256)
void split_fp32(const float* __restrict__ in, __half* __restrict__ hi,
                __half* __restrict__ lo)
{
    const size_t i = ((size_t)blockIdx.x * 256 + threadIdx.x) * 4;
    const float4 v = *reinterpret_cast<const float4*>(in + i);
    const __half h0 = __float2half_rn(v.x), h1 = __float2half_rn(v.y);
    const __half h2 = __float2half_rn(v.z), h3 = __float2half_rn(v.w);
    const __half l0 = __float2half_rn(v.x - __half2float(h0));
    const __half l1 = __float2half_rn(v.y - __half2float(h1));
    const __half l2 = __float2half_rn(v.z - __half2float(h2));
    const __half l3 = __float2half_rn(v.w - __half2float(h3));
    reinterpret_cast<__half2*>(hi + i)[0] = __halves2half2(h0, h1);
    reinterpret_cast<__half2*>(hi + i)[1] = __halves2half2(h2, h3);
    reinterpret_cast<__half2*>(lo + i)[0] = __halves2half2(l0, l1);
    reinterpret_cast<__half2*>(lo + i)[1] = __halves2half2(l2, l3);
}

// ---------------------------------------------------------------- launch
extern "C" void kernel_launch(void* const* d_in, const int* in_sizes, int n_in,
                              void* d_out, int out_size)
{
    const float* x      = (const float*)d_in[0];
    const float* W      = (const float*)d_in[1];
    const float* b      = (const float*)d_in[2];
    const float* g      = (const float*)d_in[3];
    const float* g_bias = (const float*)d_in[4];
    float* out          = (float*)d_out;

    __half *ah, *al, *bh, *bl, *hh, *hl;
    cudaGetSymbolAddress((void**)&ah, g_ah);
    cudaGetSymbolAddress((void**)&al, g_al);
    cudaGetSymbolAddress((void**)&bh, g_bh);
    cudaGetSymbolAddress((void**)&bl, g_bl);
    cudaGetSymbolAddress((void**)&hh, g_hh);
    cudaGetSymbolAddress((void**)&hl, g_hl);

    cudaFuncSetAttribute(gemm_split3<0>, cudaFuncAttributeMaxDynamicSharedMemorySize, SMEM_TOTAL);
    cudaFuncSetAttribute(gemm_split3<1>, cudaFuncAttributeMaxDynamicSharedMemorySize, SMEM_TOTAL);

    const int sgrid = (int)(NELEM / 4 / 256);        // 16384
    const dim3 ggrid(DSIZE / BN, DSIZE / BM);        // (16, 32)

    split_fp32<<<sgrid, 256>>>(x, ah, al);
    split_fp32<<<sgrid, 256>>>(W, bh, bl);
    // h = x @ W^T + b, written directly as fp16 hi/lo split
    gemm_split3<0><<<ggrid, NTHREADS, SMEM_TOTAL>>>(ah, al, bh, bl, b,
                                                    nullptr, hh, hl);
    // reuse bh/bl for g (stream-ordered after gemm1 finished reading them)
    split_fp32<<<sgrid, 256>>>(g, bh, bl);
    // out = flip(cos(h @ g^T + g_bias))
    gemm_split3<1><<<ggrid, NTHREADS, SMEM_TOTAL>>>(hh, hl, bh, bl, g_bias,
                                                    out, nullptr, nullptr);
}

// round 9
// speedup vs baseline: 1.2683x; 1.2683x over previous
#include <cuda_runtime.h>
#include <cuda_fp16.h>
#include <cstdint>
#include <math.h>

#define DSIZE 4096
#define NELEM ((size_t)DSIZE * (size_t)DSIZE)

// Static __device__ scratch (sanctioned no-alloc mechanism): 8 x 32 MB fp16
__device__ __align__(256) __half g_ah[NELEM];
__device__ __align__(256) __half g_al[NELEM];
__device__ __align__(256) __half g_bh[NELEM];
__device__ __align__(256) __half g_bl[NELEM];
__device__ __align__(256) __half g_hh[NELEM];
__device__ __align__(256) __half g_hl[NELEM];
__device__ __align__(256) __half g_gh[NELEM];
__device__ __align__(256) __half g_gl[NELEM];

// ---------------------------------------------------------------- tile config
#define BM 128
#define BN 128
#define BK 32
#define NTHREADS 256
#define STAGES 3
#define NCHUNK (DSIZE / BK)            // 128

#define OFF_AH 0
#define OFF_AL 8192
#define OFF_BH 16384
#define OFF_BL 24576
#define STAGE_BYTES 32768
#define SMEM_TOTAL (STAGES * STAGE_BYTES)   // 98304 per CTA -> 2 CTAs/SM

// ---------------------------------------------------------------- asm helpers
__device__ __forceinline__ uint32_t smem_u32(const void* p) {
    uint32_t a;
    asm("{ .reg .u64 t; cvta.to.shared.u64 t, %1; cvt.u32.u64 %0, t; }" : "=r"(a) : "l"(p));
    return a;
}
#define CP_COMMIT() asm volatile("cp.async.commit_group;" ::: "memory")
#define CP_WAIT(N)  asm volatile("cp.async.wait_group %0;" :: "n"(N) : "memory")

__device__ __forceinline__ void ldsm4(uint32_t* r, uint32_t addr) {
    asm volatile("ldmatrix.sync.aligned.m8n8.x4.shared.b16 {%0,%1,%2,%3}, [%4];"
                 : "=r"(r[0]), "=r"(r[1]), "=r"(r[2]), "=r"(r[3]) : "r"(addr));
}
__device__ __forceinline__ void mma16816(float* d, const uint32_t* a, const uint32_t* b) {
    asm volatile("mma.sync.aligned.m16n8k16.row.col.f32.f16.f16.f32 "
                 "{%0,%1,%2,%3}, {%4,%5,%6,%7}, {%8,%9}, {%0,%1,%2,%3};"
                 : "+f"(d[0]), "+f"(d[1]), "+f"(d[2]), "+f"(d[3])
                 : "r"(a[0]), "r"(a[1]), "r"(a[2]), "r"(a[3]), "r"(b[0]), "r"(b[1]));
}

// Copy one [128 x 32 fp16] tile (64B rows) into XOR-swizzled smem.
// Swizzle: seg' = seg ^ ((row >> 1) & 3) — conflict-free STS.128 + ldmatrix.
__device__ __forceinline__ void load_tile(uint32_t dst, const __half* src,
                                          int row0, int k0, int tid) {
    const char* gbase = reinterpret_cast<const char*>(src + (size_t)row0 * DSIZE + k0);
    #pragma unroll
    for (int t = 0; t < 2; t++) {
        const int i = tid + t * NTHREADS;       // 0..511
        const uint32_t r = (uint32_t)i >> 2;
        const uint32_t seg = (uint32_t)i & 3;
        const uint32_t sw = seg ^ ((r >> 1) & 3);
        asm volatile("cp.async.cg.shared.global [%0], [%1], 16;"
                     :: "r"(dst + r * 64 + sw * 16),
                        "l"(gbase + (size_t)r * (DSIZE * 2) + seg * 16));
    }
}

__device__ __forceinline__ void load_stage(uint32_t st,
                                           const __half* Ah, const __half* Al,
                                           const __half* Bh, const __half* Bl,
                                           int bm, int bn, int k0, int tid) {
    load_tile(st + OFF_AH, Ah, bm, k0, tid);
    load_tile(st + OFF_AL, Al, bm, k0, tid);
    load_tile(st + OFF_BH, Bh, bn, k0, tid);
    load_tile(st + OFF_BL, Bl, bn, k0, tid);
}

// ---------------------------------------------------------------- GEMM kernel
// C = (Ah+Al) @ (Bh+Bl)^T + bias, via 3 HMMA products (AlBl dropped, ~2^-22).
// Warp tile 32x64: 8 warps as 4(M) x 2(N). 2 CTAs/SM.
// MODE 0: write fp16 hi/lo split of result. MODE 1: write flip(cos(result)) fp32.
template <int MODE>
__global__ __launch_bounds__(NTHREADS, 2)
void gemm_split3(const __half* __restrict__ Ah, const __half* __restrict__ Al,
                 const __half* __restrict__ Bh, const __half* __restrict__ Bl,
                 const float* __restrict__ bias,
                 float* __restrict__ outF,
                 __half* __restrict__ outH, __half* __restrict__ outL)
{
    extern __shared__ __align__(1024) char smem[];
    const uint32_t sb = smem_u32(smem);

    const int tid = threadIdx.x;
    const int lane = tid & 31;
    const int wid = tid >> 5;
    const int warp_m = wid & 3;       // 4 warps along M, 32 rows each
    const int warp_n = wid >> 2;      // 2 warps along N, 64 cols each
    const int bm = blockIdx.y * BM;
    const int bn = blockIdx.x * BN;

    float acc[2][8][4];
    #pragma unroll
    for (int mt = 0; mt < 2; mt++)
        #pragma unroll
        for (int nt = 0; nt < 8; nt++)
            #pragma unroll
            for (int j = 0; j < 4; j++)
                acc[mt][nt][j] = 0.0f;

    // Prologue: fill STAGES-1 pipeline stages
    #pragma unroll
    for (int s = 0; s < STAGES - 1; s++) {
        load_stage(sb + s * STAGE_BYTES, Ah, Al, Bh, Bl, bm, bn, s * BK, tid);
        CP_COMMIT();
    }

    uint32_t stage_cur = 0;
    for (int k = 0; k < NCHUNK; k++) {
        CP_WAIT(STAGES - 2);
        __syncthreads();

        const int kn = k + STAGES - 1;
        if (kn < NCHUNK) {
            uint32_t s_nxt = stage_cur + (STAGES - 1);
            if (s_nxt >= STAGES) s_nxt -= STAGES;
            load_stage(sb + s_nxt * STAGE_BYTES, Ah, Al, Bh, Bl, bm, bn, kn * BK, tid);
        }
        CP_COMMIT();   // commit (possibly empty) group to keep wait counts consistent

        const uint32_t sa = sb + stage_cur * STAGE_BYTES;
        stage_cur = (stage_cur + 1 == STAGES) ? 0 : stage_cur + 1;

        #pragma unroll
        for (int ks = 0; ks < 2; ks++) {
            // A fragments: 2 m-tiles x (hi, lo)
            uint32_t ah[2][4], al[2][4];
            #pragma unroll
            for (int mt = 0; mt < 2; mt++) {
                const uint32_t row = warp_m * 32 + mt * 16 + (lane & 15);
                const uint32_t seg = ks * 2 + (lane >> 4);
                const uint32_t off = row * 64 + ((seg ^ ((row >> 1) & 3)) << 4);
                ldsm4(ah[mt], sa + OFF_AH + off);
                ldsm4(al[mt], sa + OFF_AL + off);
            }
            // B fragments streamed pair-by-pair (keeps live B regs at 8)
            #pragma unroll
            for (int p = 0; p < 4; p++) {
                const uint32_t n = warp_n * 64 + p * 16 + ((lane >> 4) << 3) + (lane & 7);
                const uint32_t seg = ks * 2 + ((lane >> 3) & 1);
                const uint32_t off = n * 64 + ((seg ^ ((n >> 1) & 3)) << 4);
                uint32_t th[4], tl[4];
                ldsm4(th, sa + OFF_BH + off);
                ldsm4(tl, sa + OFF_BL + off);
                #pragma unroll
                for (int mt = 0; mt < 2; mt++) {
                    mma16816(acc[mt][2 * p],     ah[mt], th);
                    mma16816(acc[mt][2 * p + 1], ah[mt], th + 2);
                    mma16816(acc[mt][2 * p],     ah[mt], tl);
                    mma16816(acc[mt][2 * p + 1], ah[mt], tl + 2);
                    mma16816(acc[mt][2 * p],     al[mt], th);
                    mma16816(acc[mt][2 * p + 1], al[mt], th + 2);
                }
            }
        }
    }

    // ---------------------------------------------------------------- epilogue
    const int g = lane >> 2;
    const int tig = lane & 3;
    #pragma unroll
    for (int mt = 0; mt < 2; mt++) {
        #pragma unroll
        for (int nt = 0; nt < 8; nt++) {
            const int col = bn + warp_n * 64 + nt * 8 + tig * 2;
            const float2 bv = *reinterpret_cast<const float2*>(bias + col);
            const int r0 = bm + warp_m * 32 + mt * 16 + g;
            const float* a = acc[mt][nt];
            float v00 = a[0] + bv.x, v01 = a[1] + bv.y;   // row r0
            float v10 = a[2] + bv.x, v11 = a[3] + bv.y;   // row r0+8
            if (MODE == 1) {
                float c;
                c = cosf(v00); if (fabsf(c) < 0.01f) c = -c; v00 = c;
                c = cosf(v01); if (fabsf(c) < 0.01f) c = -c; v01 = c;
                c = cosf(v10); if (fabsf(c) < 0.01f) c = -c; v10 = c;
                c = cosf(v11); if (fabsf(c) < 0.01f) c = -c; v11 = c;
                *reinterpret_cast<float2*>(outF + (size_t)r0 * DSIZE + col) =
                    make_float2(v00, v01);
                *reinterpret_cast<float2*>(outF + (size_t)(r0 + 8) * DSIZE + col) =
                    make_float2(v10, v11);
            } else {
                const __half h00 = __float2half_rn(v00), h01 = __float2half_rn(v01);
                const __half h10 = __float2half_rn(v10), h11 = __float2half_rn(v11);
                const __half l00 = __float2half_rn(v00 - __half2float(h00));
                const __half l01 = __float2half_rn(v01 - __half2float(h01));
                const __half l10 = __float2half_rn(v10 - __half2float(h10));
                const __half l11 = __float2half_rn(v11 - __half2float(h11));
                *reinterpret_cast<__half2*>(outH + (size_t)r0 * DSIZE + col) =
                    __halves2half2(h00, h01);
                *reinterpret_cast<__half2*>(outH + (size_t)(r0 + 8) * DSIZE + col) =
                    __halves2half2(h10, h11);
                *reinterpret_cast<__half2*>(outL + (size_t)r0 * DSIZE + col) =
                    __halves2half2(l00, l01);
                *reinterpret_cast<__half2*>(outL + (size_t)(r0 + 8) * DSIZE + col) =
                    __halves2half2(l10, l11);
            }
        }
    }
}

// ---------------------------------------------------------------- fp32 -> fp16 hi/lo
__global__ __launch_bounds__(256)
void split_fp32(const float* __restrict__ in, __half* __restrict__ hi,
                __half* __restrict__ lo)
{
    const size_t i = ((size_t)blockIdx.x * 256 + threadIdx.x) * 4;
    const float4 v = *reinterpret_cast<const float4*>(in + i);
    const __half h0 = __float2half_rn(v.x), h1 = __float2half_rn(v.y);
    const __half h2 = __float2half_rn(v.z), h3 = __float2half_rn(v.w);
    const __half l0 = __float2half_rn(v.x - __half2float(h0));
    const __half l1 = __float2half_rn(v.y - __half2float(h1));
    const __half l2 = __float2half_rn(v.z - __half2float(h2));
    const __half l3 = __float2half_rn(v.w - __half2float(h3));
    reinterpret_cast<__half2*>(hi + i)[0] = __halves2half2(h0, h1);
    reinterpret_cast<__half2*>(hi + i)[1] = __halves2half2(h2, h3);
    reinterpret_cast<__half2*>(lo + i)[0] = __halves2half2(l0, l1);
    reinterpret_cast<__half2*>(lo + i)[1] = __halves2half2(l2, l3);
}

// ---------------------------------------------------------------- launch
// 6 launches/invocation so the ncu capture window (skip 5, capture 1)
// lands on gemm2 instead of a split kernel.
extern "C" void kernel_launch(void* const* d_in, const int* in_sizes, int n_in,
                              void* d_out, int out_size)
{
    const float* x      = (const float*)d_in[0];
    const float* W      = (const float*)d_in[1];
    const float* b      = (const float*)d_in[2];
    const float* g      = (const float*)d_in[3];
    const float* g_bias = (const float*)d_in[4];
    float* out          = (float*)d_out;

    __half *ah, *al, *bh, *bl, *hh, *hl, *gh, *gl;
    cudaGetSymbolAddress((void**)&ah, g_ah);
    cudaGetSymbolAddress((void**)&al, g_al);
    cudaGetSymbolAddress((void**)&bh, g_bh);
    cudaGetSymbolAddress((void**)&bl, g_bl);
    cudaGetSymbolAddress((void**)&hh, g_hh);
    cudaGetSymbolAddress((void**)&hl, g_hl);
    cudaGetSymbolAddress((void**)&gh, g_gh);
    cudaGetSymbolAddress((void**)&gl, g_gl);

    cudaFuncSetAttribute(gemm_split3<0>, cudaFuncAttributeMaxDynamicSharedMemorySize, SMEM_TOTAL);
    cudaFuncSetAttribute(gemm_split3<1>, cudaFuncAttributeMaxDynamicSharedMemorySize, SMEM_TOTAL);

    const int sgrid = (int)(NELEM / 4 / 256);        // 16384
    const dim3 ggrid(DSIZE / BN, DSIZE / BM);        // (32, 32)
    const size_t half = NELEM / 2;

    split_fp32<<<sgrid, 256>>>(x, ah, al);                            // 0
    split_fp32<<<sgrid, 256>>>(W, bh, bl);                            // 1
    split_fp32<<<sgrid / 2, 256>>>(g, gh, gl);                        // 2 (lower half)
    split_fp32<<<sgrid / 2, 256>>>(g + half, gh + half, gl + half);   // 3 (upper half)
    // h = x @ W^T + b, written directly as fp16 hi/lo split
    gemm_split3<0><<<ggrid, NTHREADS, SMEM_TOTAL>>>(ah, al, bh, bl, b,
                                                    nullptr, hh, hl); // 4
    // out = flip(cos(h @ g^T + g_bias))
    gemm_split3<1><<<ggrid, NTHREADS, SMEM_TOTAL>>>(hh, hl, gh, gl, g_bias,
                                                    out, nullptr, nullptr); // 5 <- profiled
}

// round 11
// speedup vs baseline: 1.2716x; 1.0026x over previous
#include <cuda_runtime.h>
#include <cuda_fp16.h>
#include <cstdint>
#include <math.h>

#define DSIZE 4096
#define NELEM ((size_t)DSIZE * (size_t)DSIZE)

// Static __device__ scratch (sanctioned no-alloc mechanism): 8 x 32 MB fp16
__device__ __align__(256) __half g_ah[NELEM];
__device__ __align__(256) __half g_al[NELEM];
__device__ __align__(256) __half g_bh[NELEM];
__device__ __align__(256) __half g_bl[NELEM];
__device__ __align__(256) __half g_hh[NELEM];
__device__ __align__(256) __half g_hl[NELEM];
__device__ __align__(256) __half g_gh[NELEM];
__device__ __align__(256) __half g_gl[NELEM];

// ---------------------------------------------------------------- tile config
#define BM 128
#define BN 128
#define BK 32
#define NTHREADS 256
#define STAGES 3
#define NCHUNK (DSIZE / BK)            // 128

#define OFF_AH 0
#define OFF_AL 8192
#define OFF_BH 16384
#define OFF_BL 24576
#define STAGE_BYTES 32768
#define SMEM_TOTAL (STAGES * STAGE_BYTES)   // 98304 per CTA -> 2 CTAs/SM

// ---------------------------------------------------------------- asm helpers
__device__ __forceinline__ uint32_t smem_u32(const void* p) {
    uint32_t a;
    asm("{ .reg .u64 t; cvta.to.shared.u64 t, %1; cvt.u32.u64 %0, t; }" : "=r"(a) : "l"(p));
    return a;
}
#define CP_COMMIT() asm volatile("cp.async.commit_group;" ::: "memory")
#define CP_WAIT(N)  asm volatile("cp.async.wait_group %0;" :: "n"(N) : "memory")

__device__ __forceinline__ void ldsm4(uint32_t* r, uint32_t addr) {
    asm volatile("ldmatrix.sync.aligned.m8n8.x4.shared.b16 {%0,%1,%2,%3}, [%4];"
                 : "=r"(r[0]), "=r"(r[1]), "=r"(r[2]), "=r"(r[3]) : "r"(addr));
}
__device__ __forceinline__ void mma16816(float* d, const uint32_t* a, const uint32_t* b) {
    asm volatile("mma.sync.aligned.m16n8k16.row.col.f32.f16.f16.f32 "
                 "{%0,%1,%2,%3}, {%4,%5,%6,%7}, {%8,%9}, {%0,%1,%2,%3};"
                 : "+f"(d[0]), "+f"(d[1]), "+f"(d[2]), "+f"(d[3])
                 : "r"(a[0]), "r"(a[1]), "r"(a[2]), "r"(a[3]), "r"(b[0]), "r"(b[1]));
}

// Copy one [128 x 32 fp16] tile (64B rows) into XOR-swizzled smem.
// Swizzle: seg' = seg ^ ((row >> 1) & 3) — conflict-free STS.128 + ldmatrix.
__device__ __forceinline__ void load_tile(uint32_t dst, const __half* src,
                                          int row0, int k0, int tid) {
    const char* gbase = reinterpret_cast<const char*>(src + (size_t)row0 * DSIZE + k0);
    #pragma unroll
    for (int t = 0; t < 2; t++) {
        const int i = tid + t * NTHREADS;       // 0..511
        const uint32_t r = (uint32_t)i >> 2;
        const uint32_t seg = (uint32_t)i & 3;
        const uint32_t sw = seg ^ ((r >> 1) & 3);
        asm volatile("cp.async.cg.shared.global [%0], [%1], 16;"
                     :: "r"(dst + r * 64 + sw * 16),
                        "l"(gbase + (size_t)r * (DSIZE * 2) + seg * 16));
    }
}

__device__ __forceinline__ void load_stage(uint32_t st,
                                           const __half* Ah, const __half* Al,
                                           const __half* Bh, const __half* Bl,
                                           int bm, int bn, int k0, int tid) {
    load_tile(st + OFF_AH, Ah, bm, k0, tid);
    load_tile(st + OFF_AL, Al, bm, k0, tid);
    load_tile(st + OFF_BH, Bh, bn, k0, tid);
    load_tile(st + OFF_BL, Bl, bn, k0, tid);
}

// ---------------------------------------------------------------- GEMM kernel
// C = (Ah+Al) @ (Bh+Bl)^T + bias, via 3 HMMA products (AlBl dropped, ~2^-22).
// Warp tile 32x64: 8 warps as 4(M) x 2(N). 2 CTAs/SM.
// MODE 0: write fp16 hi/lo split of result. MODE 1: write flip(cos(result)) fp32.
template <int MODE>
__global__ __launch_bounds__(NTHREADS, 2)
void gemm_split3(const __half* __restrict__ Ah, const __half* __restrict__ Al,
                 const __half* __restrict__ Bh, const __half* __restrict__ Bl,
                 const float* __restrict__ bias,
                 float* __restrict__ outF,
                 __half* __restrict__ outH, __half* __restrict__ outL)
{
    extern __shared__ __align__(1024) char smem[];
    const uint32_t sb = smem_u32(smem);

    const int tid = threadIdx.x;
    const int lane = tid & 31;
    const int wid = tid >> 5;
    const int warp_m = wid & 3;       // 4 warps along M, 32 rows each
    const int warp_n = wid >> 2;      // 2 warps along N, 64 cols each
    const int bm = blockIdx.y * BM;
    const int bn = blockIdx.x * BN;

    float acc[2][8][4];
    #pragma unroll
    for (int mt = 0; mt < 2; mt++)
        #pragma unroll
        for (int nt = 0; nt < 8; nt++)
            #pragma unroll
            for (int j = 0; j < 4; j++)
                acc[mt][nt][j] = 0.0f;

    // Prologue: fill STAGES-1 pipeline stages
    #pragma unroll
    for (int s = 0; s < STAGES - 1; s++) {
        load_stage(sb + s * STAGE_BYTES, Ah, Al, Bh, Bl, bm, bn, s * BK, tid);
        CP_COMMIT();
    }

    uint32_t stage_cur = 0;
    for (int k = 0; k < NCHUNK; k++) {
        CP_WAIT(STAGES - 2);
        __syncthreads();

        const int kn = k + STAGES - 1;
        if (kn < NCHUNK) {
            uint32_t s_nxt = stage_cur + (STAGES - 1);
            if (s_nxt >= STAGES) s_nxt -= STAGES;
            load_stage(sb + s_nxt * STAGE_BYTES, Ah, Al, Bh, Bl, bm, bn, kn * BK, tid);
        }
        CP_COMMIT();   // commit (possibly empty) group to keep wait counts consistent

        const uint32_t sa = sb + stage_cur * STAGE_BYTES;
        stage_cur = (stage_cur + 1 == STAGES) ? 0 : stage_cur + 1;

        #pragma unroll
        for (int ks = 0; ks < 2; ks++) {
            // A fragments: 2 m-tiles x (hi, lo)
            uint32_t ah[2][4], al[2][4];
            #pragma unroll
            for (int mt = 0; mt < 2; mt++) {
                const uint32_t row = warp_m * 32 + mt * 16 + (lane & 15);
                const uint32_t seg = ks * 2 + (lane >> 4);
                const uint32_t off = row * 64 + ((seg ^ ((row >> 1) & 3)) << 4);
                ldsm4(ah[mt], sa + OFF_AH + off);
                ldsm4(al[mt], sa + OFF_AL + off);
            }
            // B fragments streamed pair-by-pair (keeps live B regs at 8)
            #pragma unroll
            for (int p = 0; p < 4; p++) {
                const uint32_t n = warp_n * 64 + p * 16 + ((lane >> 4) << 3) + (lane & 7);
                const uint32_t seg = ks * 2 + ((lane >> 3) & 1);
                const uint32_t off = n * 64 + ((seg ^ ((n >> 1) & 3)) << 4);
                uint32_t th[4], tl[4];
                ldsm4(th, sa + OFF_BH + off);
                ldsm4(tl, sa + OFF_BL + off);
                #pragma unroll
                for (int mt = 0; mt < 2; mt++) {
                    mma16816(acc[mt][2 * p],     ah[mt], th);
                    mma16816(acc[mt][2 * p + 1], ah[mt], th + 2);
                    mma16816(acc[mt][2 * p],     ah[mt], tl);
                    mma16816(acc[mt][2 * p + 1], ah[mt], tl + 2);
                    mma16816(acc[mt][2 * p],     al[mt], th);
                    mma16816(acc[mt][2 * p + 1], al[mt], th + 2);
                }
            }
        }
    }

    // ---------------------------------------------------------------- epilogue
    const int g = lane >> 2;
    const int tig = lane & 3;
    #pragma unroll
    for (int mt = 0; mt < 2; mt++) {
        #pragma unroll
        for (int nt = 0; nt < 8; nt++) {
            const int col = bn + warp_n * 64 + nt * 8 + tig * 2;
            const float2 bv = *reinterpret_cast<const float2*>(bias + col);
            const int r0 = bm + warp_m * 32 + mt * 16 + g;
            const float* a = acc[mt][nt];
            float v00 = a[0] + bv.x, v01 = a[1] + bv.y;   // row r0
            float v10 = a[2] + bv.x, v11 = a[3] + bv.y;   // row r0+8
            if (MODE == 1) {
                float c;
                c = cosf(v00); if (fabsf(c) < 0.01f) c = -c; v00 = c;
                c = cosf(v01); if (fabsf(c) < 0.01f) c = -c; v01 = c;
                c = cosf(v10); if (fabsf(c) < 0.01f) c = -c; v10 = c;
                c = cosf(v11); if (fabsf(c) < 0.01f) c = -c; v11 = c;
                *reinterpret_cast<float2*>(outF + (size_t)r0 * DSIZE + col) =
                    make_float2(v00, v01);
                *reinterpret_cast<float2*>(outF + (size_t)(r0 + 8) * DSIZE + col) =
                    make_float2(v10, v11);
            } else {
                const __half h00 = __float2half_rn(v00), h01 = __float2half_rn(v01);
                const __half h10 = __float2half_rn(v10), h11 = __float2half_rn(v11);
                const __half l00 = __float2half_rn(v00 - __half2float(h00));
                const __half l01 = __float2half_rn(v01 - __half2float(h01));
                const __half l10 = __float2half_rn(v10 - __half2float(h10));
                const __half l11 = __float2half_rn(v11 - __half2float(h11));
                *reinterpret_cast<__half2*>(outH + (size_t)r0 * DSIZE + col) =
                    __halves2half2(h00, h01);
                *reinterpret_cast<__half2*>(outH + (size_t)(r0 + 8) * DSIZE + col) =
                    __halves2half2(h10, h11);
                *reinterpret_cast<__half2*>(outL + (size_t)r0 * DSIZE + col) =
                    __halves2half2(l00, l01);
                *reinterpret_cast<__half2*>(outL + (size_t)(r0 + 8) * DSIZE + col) =
                    __halves2half2(l10, l11);
            }
        }
    }
}

// ---------------------------------------------------------------- fp32 -> fp16 hi/lo
__global__ __launch_bounds__(256)
void split_fp32(const float* __restrict__ in, __half* __restrict__ hi,
                __half* __restrict__ lo)
{
    const size_t i = ((size_t)blockIdx.x * 256 + threadIdx.x) * 4;
    const float4 v = *reinterpret_cast<const float4*>(in + i);
    const __half h0 = __float2half_rn(v.x), h1 = __float2half_rn(v.y);
    const __half h2 = __float2half_rn(v.z), h3 = __float2half_rn(v.w);
    const __half l0 = __float2half_rn(v.x - __half2float(h0));
    const __half l1 = __float2half_rn(v.y - __half2float(h1));
    const __half l2 = __float2half_rn(v.z - __half2float(h2));
    const __half l3 = __float2half_rn(v.w - __half2float(h3));
    reinterpret_cast<__half2*>(hi + i)[0] = __halves2half2(h0, h1);
    reinterpret_cast<__half2*>(hi + i)[1] = __halves2half2(h2, h3);
    reinterpret_cast<__half2*>(lo + i)[0] = __halves2half2(l0, l1);
    reinterpret_cast<__half2*>(lo + i)[1] = __halves2half2(l2, l3);
}

// ---------------------------------------------------------------- launch
// Launch order puts gemm1 at index 3: the ncu capture window has landed on
// absolute launch index 3 in both prior profiled rounds (R6: split g 16384,
// R9: split g-half 8192) — this round it captures the GEMM.
extern "C" void kernel_launch(void* const* d_in, const int* in_sizes, int n_in,
                              void* d_out, int out_size)
{
    const float* x      = (const float*)d_in[0];
    const float* W      = (const float*)d_in[1];
    const float* b      = (const float*)d_in[2];
    const float* g      = (const float*)d_in[3];
    const float* g_bias = (const float*)d_in[4];
    float* out          = (float*)d_out;

    __half *ah, *al, *bh, *bl, *hh, *hl, *gh, *gl;
    cudaGetSymbolAddress((void**)&ah, g_ah);
    cudaGetSymbolAddress((void**)&al, g_al);
    cudaGetSymbolAddress((void**)&bh, g_bh);
    cudaGetSymbolAddress((void**)&bl, g_bl);
    cudaGetSymbolAddress((void**)&hh, g_hh);
    cudaGetSymbolAddress((void**)&hl, g_hl);
    cudaGetSymbolAddress((void**)&gh, g_gh);
    cudaGetSymbolAddress((void**)&gl, g_gl);

    cudaFuncSetAttribute(gemm_split3<0>, cudaFuncAttributeMaxDynamicSharedMemorySize, SMEM_TOTAL);
    cudaFuncSetAttribute(gemm_split3<1>, cudaFuncAttributeMaxDynamicSharedMemorySize, SMEM_TOTAL);

    const int sgrid = (int)(NELEM / 4 / 256);        // 16384
    const dim3 ggrid(DSIZE / BN, DSIZE / BM);        // (32, 32)

    split_fp32<<<sgrid, 256>>>(x, ah, al);                            // 0
    split_fp32<<<sgrid, 256>>>(W, bh, bl);                            // 1
    split_fp32<<<sgrid, 256>>>(g, gh, gl);                            // 2
    // h = x @ W^T + b, written directly as fp16 hi/lo split
    gemm_split3<0><<<ggrid, NTHREADS, SMEM_TOTAL>>>(ah, al, bh, bl, b,
                                                    nullptr, hh, hl); // 3 <- profiled
    // out = flip(cos(h @ g^T + g_bias))
    gemm_split3<1><<<ggrid, NTHREADS, SMEM_TOTAL>>>(hh, hl, gh, gl, g_bias,
                                                    out, nullptr, nullptr); // 4
}